// round 17
// baseline (speedup 1.0000x reference)
#include <cuda_runtime.h>

#define N_NODES 100000
#define N_EDGES 1600000
#define IN_DIM  256
#define OUT_DIM 128
#define BATCH   8192
#define CAP     192
#define SLOPE   0.1f
#define EPS     1e-8f

#define MARK_BLKS 32
#define PREP_BLKS 8
#define FRONT_GRID (MARK_BLKS + PREP_BLKS + 1)

typedef unsigned long long u64;

// ---------------- f32x2 packed helpers (Blackwell dual-FMA) ----------------
__device__ __forceinline__ u64 pk2(float lo, float hi) {
    u64 d;
    asm("mov.b64 %0, {%1, %2};" : "=l"(d) : "r"(__float_as_uint(lo)), "r"(__float_as_uint(hi)));
    return d;
}
__device__ __forceinline__ void upk2(u64 v, float& lo, float& hi) {
    unsigned int a, b;
    asm("mov.b64 {%0, %1}, %2;" : "=r"(a), "=r"(b) : "l"(v));
    lo = __uint_as_float(a); hi = __uint_as_float(b);
}
__device__ __forceinline__ void fma2(u64& d, u64 a, u64 b) {
    asm("fma.rn.f32x2 %0, %1, %2, %3;" : "=l"(d) : "l"(a), "l"(b), "l"(d));
}
__device__ __forceinline__ u64 d2l(double x) { return __double_as_longlong(x); }
__device__ __forceinline__ float hsum2(u64 v) {
    float lo, hi; upk2(v, lo, hi); return lo + hi;
}

// ---------------- static device scratch ----------------
__device__ unsigned g_epoch = 1;               // bumped by k_gemm each launch; 1 beats zero-init slots
__device__ int   g_is64;
__device__ __align__(16) float g_v1[IN_DIM];   // W @ a[:128]
__device__ __align__(16) float g_v2[IN_DIM];   // W @ a[128:]
__device__ float g_c1, g_c2;                   // b.a[:128], b.a[128:]
__device__ unsigned g_slot[N_NODES];           // (epoch<<13)|pos ; stale epochs never match
__device__ int   g_cnt[BATCH];
__device__ int   g_rep[BATCH];
__device__ __align__(16) int g_gc[BATCH * CAP];
__device__ __align__(16) float g_agg[BATCH * IN_DIM];
__device__ float g_denom[BATCH];

__device__ __forceinline__ int load_idx(const void* p, int i, int is64) {
    if (is64) return (int)((const long long*)p)[i];
    return ((const int*)p)[i];
}

// ---------------- K_front: mark(+cnt zero, self-detect) | prep (8 blocks, ILP) | r-detect ----------------
__global__ __launch_bounds__(256) void k_front(const float* __restrict__ W,
                                               const float* __restrict__ b,
                                               const float* __restrict__ a,
                                               const void* __restrict__ rp,
                                               const void* __restrict__ bidx) {
    int blk = blockIdx.x;
    int t = threadIdx.x;

    if (blk < MARK_BLKS) {
        __shared__ int s_is64;
        if (t < 32) {
            const long long* b64 = (const long long*)bidx;
            long long v0 = b64[t * 64];
            long long v1 = b64[t * 64 + 2048];
            int ok = (v0 >= 0 && v0 < N_NODES) && (v1 >= 0 && v1 < N_NODES);
            int all = __all_sync(0xffffffffu, ok);
            if (t == 0) s_is64 = all;
        }
        int i = blk * 256 + t;
        g_cnt[i] = 0;
        __syncthreads();
        int node = load_idx(bidx, i, s_is64);
        unsigned ep = g_epoch;
        atomicMax(&g_slot[node], (ep << 13) | (unsigned)i);
        return;
    }

    if (blk == MARK_BLKS + PREP_BLKS) {
        if (t < 32) {
            const long long* r64 = (const long long*)rp;
            const long long stride = (N_EDGES / 2) / 64;
            long long v0 = r64[(long long)t * stride];
            long long v1 = r64[(long long)(t + 32) * stride];
            int ok = (v0 >= 0 && v0 < N_NODES) && (v1 >= 0 && v1 < N_NODES);
            int all = __all_sync(0xffffffffu, ok);
            if (t == 0) g_is64 = all;
        }
        return;
    }

    // prep: 8 blocks, 32 W-rows each; 4 rows/warp, 8 interleaved shuffle chains
    int p = blk - MARK_BLKS;
    __shared__ float sa[2 * OUT_DIM];
    __shared__ float sb1[OUT_DIM], sb2[OUT_DIM];
    if (t < 2 * OUT_DIM) sa[t] = a[t];
    if (p == 0 && t < OUT_DIM) {
        float bb = b[t];
        sb1[t] = bb * a[t];
        sb2[t] = bb * a[OUT_DIM + t];
    }
    __syncthreads();

    int w = t >> 5, l = t & 31;
    int k0 = p * 32 + w * 4;
    int j = l * 4;
    float4 wv[4];
#pragma unroll
    for (int r = 0; r < 4; r++)
        wv[r] = *(const float4*)&W[(size_t)(k0 + r) * OUT_DIM + j];

    float s1v[4], s2v[4];
#pragma unroll
    for (int r = 0; r < 4; r++) {
        s1v[r] = wv[r].x * sa[j]               + wv[r].y * sa[j + 1]
               + wv[r].z * sa[j + 2]           + wv[r].w * sa[j + 3];
        s2v[r] = wv[r].x * sa[OUT_DIM + j]     + wv[r].y * sa[OUT_DIM + j + 1]
               + wv[r].z * sa[OUT_DIM + j + 2] + wv[r].w * sa[OUT_DIM + j + 3];
    }
#pragma unroll
    for (int off = 16; off; off >>= 1) {
#pragma unroll
        for (int r = 0; r < 4; r++) {
            s1v[r] += __shfl_xor_sync(0xffffffffu, s1v[r], off);
            s2v[r] += __shfl_xor_sync(0xffffffffu, s2v[r], off);
        }
    }
    if (l == 0) {
#pragma unroll
        for (int r = 0; r < 4; r++) {
            g_v1[k0 + r] = s1v[r];
            g_v2[k0 + r] = s2v[r];
        }
    }

    if (p == 0) {
        __syncthreads();
        if (t == 0) {
            float t1 = 0.f, t2 = 0.f;
            for (int jj = 0; jj < OUT_DIM; jj++) { t1 += sb1[jj]; t2 += sb2[jj]; }
            g_c1 = t1; g_c2 = t2;
        }
    }
}

// ---------------- K_edge: filter via epoch-tagged slot, bucket c; 4 edges / thread ----------------
__global__ __launch_bounds__(256) void k_edge(const void* __restrict__ rp,
                                              const void* __restrict__ cp) {
    int base = (blockIdx.x * blockDim.x + threadIdx.x) * 4;
    if (base >= N_EDGES) return;     // N_EDGES % 4 == 0
    int is64 = g_is64;
    unsigned ep = g_epoch;
    int r[4];
    if (is64) {
        longlong4 rr = ((const longlong4*)rp)[base >> 2];
        r[0] = (int)rr.x; r[1] = (int)rr.y; r[2] = (int)rr.z; r[3] = (int)rr.w;
    } else {
        int4 rr = ((const int4*)rp)[base >> 2];
        r[0] = rr.x; r[1] = rr.y; r[2] = rr.z; r[3] = rr.w;
    }
    unsigned v[4];
#pragma unroll
    for (int k = 0; k < 4; k++) v[k] = g_slot[r[k]];
#pragma unroll
    for (int k = 0; k < 4; k++) {
        if ((v[k] >> 13) == ep) {
            int slot = v[k] & 8191;
            int c = load_idx(cp, base + k, is64);
            int pos = atomicAdd(&g_cnt[slot], 1);
            if (pos < CAP) g_gc[slot * CAP + pos] = c;
        }
    }
}

// ---------------- K_agg: warp per rep slot; 4-edge ILP, f32x2 ----------------
__global__ __launch_bounds__(128) void k_agg(const float* __restrict__ feats,
                                             const void* __restrict__ bidx) {
    int gw   = (blockIdx.x * blockDim.x + threadIdx.x) >> 5;
    int lane = threadIdx.x & 31;
    if (gw >= BATCH) return;
    int node = load_idx(bidx, gw, g_is64);
    int rep = (int)(g_slot[node] & 8191u);
    if (lane == 0) g_rep[gw] = rep;
    if (rep != gw) return;

    u64 v2p[4];
#pragma unroll
    for (int t = 0; t < 4; t++) v2p[t] = d2l(((const double*)g_v2)[lane * 4 + t]);

    float ssrc;
    {
        u64 v1p[4];
#pragma unroll
        for (int t = 0; t < 4; t++) v1p[t] = d2l(((const double*)g_v1)[lane * 4 + t]);
        const double2* rown = (const double2*)(feats + (size_t)node * IN_DIM);
        double2 rA = rown[lane * 2];
        double2 rB = rown[lane * 2 + 1];
        u64 sv2 = 0ull;
        fma2(sv2, d2l(rA.x), v1p[0]);
        fma2(sv2, d2l(rA.y), v1p[1]);
        fma2(sv2, d2l(rB.x), v1p[2]);
        fma2(sv2, d2l(rB.y), v1p[3]);
        float sv = hsum2(sv2);
#pragma unroll
        for (int off = 16; off; off >>= 1) sv += __shfl_xor_sync(0xffffffffu, sv, off);
        ssrc = sv + g_c1 + g_c2;
    }

    int n = g_cnt[gw];
    if (n > CAP) n = CAP;
    const int* gc = &g_gc[gw * CAP];

    if (n == 0) {
        double2 z = make_double2(0.0, 0.0);
        *(double2*)&g_agg[gw * IN_DIM + lane * 8] = z;
        *(double2*)&g_agg[gw * IN_DIM + lane * 8 + 4] = z;
        if (lane == 0) g_denom[gw] = 0.f;
        return;
    }

    u64 acc2[4] = {0ull, 0ull, 0ull, 0ull};
    float dsum = 0.f;

    for (int base = 0; base < n; base += 4) {
        int4 gci = *(const int4*)(gc + base);
        int c0 = gci.x;
        int c1i = (base + 1 < n) ? gci.y : c0;
        int c2i = (base + 2 < n) ? gci.z : c0;
        int c3i = (base + 3 < n) ? gci.w : c0;
        const double2* R0 = (const double2*)(feats + (size_t)c0  * IN_DIM);
        const double2* R1 = (const double2*)(feats + (size_t)c1i * IN_DIM);
        const double2* R2 = (const double2*)(feats + (size_t)c2i * IN_DIM);
        const double2* R3 = (const double2*)(feats + (size_t)c3i * IN_DIM);

        double2 x0a = R0[lane * 2], x0b = R0[lane * 2 + 1];
        double2 x1a = R1[lane * 2], x1b = R1[lane * 2 + 1];
        double2 x2a = R2[lane * 2], x2b = R2[lane * 2 + 1];
        double2 x3a = R3[lane * 2], x3b = R3[lane * 2 + 1];

        u64 p0 = 0ull, p1 = 0ull, p2 = 0ull, p3 = 0ull;
        fma2(p0, d2l(x0a.x), v2p[0]); fma2(p1, d2l(x1a.x), v2p[0]);
        fma2(p2, d2l(x2a.x), v2p[0]); fma2(p3, d2l(x3a.x), v2p[0]);
        fma2(p0, d2l(x0a.y), v2p[1]); fma2(p1, d2l(x1a.y), v2p[1]);
        fma2(p2, d2l(x2a.y), v2p[1]); fma2(p3, d2l(x3a.y), v2p[1]);
        fma2(p0, d2l(x0b.x), v2p[2]); fma2(p1, d2l(x1b.x), v2p[2]);
        fma2(p2, d2l(x2b.x), v2p[2]); fma2(p3, d2l(x3b.x), v2p[2]);
        fma2(p0, d2l(x0b.y), v2p[3]); fma2(p1, d2l(x1b.y), v2p[3]);
        fma2(p2, d2l(x2b.y), v2p[3]); fma2(p3, d2l(x3b.y), v2p[3]);

        float s0 = hsum2(p0), s1 = hsum2(p1), s2 = hsum2(p2), s3 = hsum2(p3);
#pragma unroll
        for (int off = 16; off; off >>= 1) {
            s0 += __shfl_xor_sync(0xffffffffu, s0, off);
            s1 += __shfl_xor_sync(0xffffffffu, s1, off);
            s2 += __shfl_xor_sync(0xffffffffu, s2, off);
            s3 += __shfl_xor_sync(0xffffffffu, s3, off);
        }
        float y0 = ssrc + s0, y1 = ssrc + s1, y2 = ssrc + s2, y3 = ssrc + s3;
        float w0 = __expf(y0 > 0.f ? y0 : SLOPE * y0);
        float w1 = __expf(y1 > 0.f ? y1 : SLOPE * y1);
        float w2 = __expf(y2 > 0.f ? y2 : SLOPE * y2);
        float w3 = __expf(y3 > 0.f ? y3 : SLOPE * y3);
        if (base + 1 >= n) w1 = 0.f;
        if (base + 2 >= n) w2 = 0.f;
        if (base + 3 >= n) w3 = 0.f;
        dsum += (w0 + w1) + (w2 + w3);

        u64 wd0 = pk2(w0, w0), wd1 = pk2(w1, w1), wd2 = pk2(w2, w2), wd3 = pk2(w3, w3);
        fma2(acc2[0], wd0, d2l(x0a.x)); fma2(acc2[1], wd0, d2l(x0a.y));
        fma2(acc2[2], wd0, d2l(x0b.x)); fma2(acc2[3], wd0, d2l(x0b.y));
        fma2(acc2[0], wd1, d2l(x1a.x)); fma2(acc2[1], wd1, d2l(x1a.y));
        fma2(acc2[2], wd1, d2l(x1b.x)); fma2(acc2[3], wd1, d2l(x1b.y));
        fma2(acc2[0], wd2, d2l(x2a.x)); fma2(acc2[1], wd2, d2l(x2a.y));
        fma2(acc2[2], wd2, d2l(x2b.x)); fma2(acc2[3], wd2, d2l(x2b.y));
        fma2(acc2[0], wd3, d2l(x3a.x)); fma2(acc2[1], wd3, d2l(x3a.y));
        fma2(acc2[2], wd3, d2l(x3b.x)); fma2(acc2[3], wd3, d2l(x3b.y));
    }
    *(double2*)&g_agg[gw * IN_DIM + lane * 8] =
        make_double2(__longlong_as_double(acc2[0]), __longlong_as_double(acc2[1]));
    *(double2*)&g_agg[gw * IN_DIM + lane * 8 + 4] =
        make_double2(__longlong_as_double(acc2[2]), __longlong_as_double(acc2[3]));
    if (lane == 0) g_denom[gw] = dsum;
}

// ---------------- K_gemm: N-split 64 rows x 64 cols per block; grid 256; f32x2 col-pairs ----------------
// ty=tid>>4 (16 row-groups of 4), tx=tid&15 (16 col-groups of 4).
// Warp: 2 distinct A addrs (broadcast, 1 cyc) + 16 distinct B float4 (256B, 2 cyc) per k.
#define GBM 64
#define GBN 64
#define GBK 32
__global__ __launch_bounds__(256) void k_gemm(const float* __restrict__ W,
                                              const float* __restrict__ bvec,
                                              float* __restrict__ out) {
    __shared__ float As[GBK][GBM + 4];
    __shared__ float Bs[GBK][GBN];
    __shared__ int   reps[GBM];
    __shared__ float dns[GBM];
    int tid = threadIdx.x;
    int ty = tid >> 4;                    // 0..15 row-group
    int tx = tid & 15;                    // 0..15 col-group
    int rb = blockIdx.x >> 1;
    int nh = blockIdx.x & 1;              // column half
    int rowBase = rb * GBM;
    int colBase = nh * GBN;

    if (blockIdx.x == 0 && tid == 0) g_epoch = g_epoch + 1;   // retire this launch's epoch

    if (tid < GBM) {
        int rp = g_rep[rowBase + tid];
        reps[tid] = rp;
        dns[tid] = g_denom[rp];
    }
    __syncthreads();

    u64 acc[4][2] = {};                   // [row r][col-pair cp]

    for (int k0 = 0; k0 < IN_DIM; k0 += GBK) {
#pragma unroll
        for (int i = 0; i < 2; i++) {     // A tile: 64 rows x 32 k = 512 float4
            int idx = tid + i * 256;
            int r = idx >> 3;             // 0..63
            int kk = (idx & 7) << 2;
            float4 v = *(const float4*)&g_agg[(size_t)reps[r] * IN_DIM + k0 + kk];
            As[kk][r]     = v.x;
            As[kk + 1][r] = v.y;
            As[kk + 2][r] = v.z;
            As[kk + 3][r] = v.w;
        }
#pragma unroll
        for (int i = 0; i < 2; i++) {     // B tile: 32 k x 64 cols = 512 float4
            int f = tid + i * 256;
            int kk = f >> 4;              // 0..31
            int cc = (f & 15) << 2;       // 0..60
            *(float4*)&Bs[kk][cc] = *(const float4*)&W[(size_t)(k0 + kk) * OUT_DIM + colBase + cc];
        }
        __syncthreads();
#pragma unroll
        for (int k = 0; k < GBK; k++) {
            float4 av = *(const float4*)&As[k][ty * 4];       // 2-addr broadcast per warp
            double2 bb = *(const double2*)&Bs[k][tx * 4];     // 2 natural col-pairs
            u64 b0 = d2l(bb.x), b1 = d2l(bb.y);
            u64 a0 = pk2(av.x, av.x);
            u64 a1 = pk2(av.y, av.y);
            u64 a2 = pk2(av.z, av.z);
            u64 a3 = pk2(av.w, av.w);
            fma2(acc[0][0], a0, b0); fma2(acc[0][1], a0, b1);
            fma2(acc[1][0], a1, b0); fma2(acc[1][1], a1, b1);
            fma2(acc[2][0], a2, b0); fma2(acc[2][1], a2, b1);
            fma2(acc[3][0], a3, b0); fma2(acc[3][1], a3, b1);
        }
        __syncthreads();
    }

    float4 bv = *(const float4*)&bvec[colBase + tx * 4];
#pragma unroll
    for (int r = 0; r < 4; r++) {
        int lrow = ty * 4 + r;
        int row = rowBase + lrow;
        float dn = dns[lrow];
        float inv = 1.0f / (dn + EPS);
        float c0, c1, c2, c3;
        upk2(acc[r][0], c0, c1);
        upk2(acc[r][1], c2, c3);
        float4 o;
        o.x = (c0 + dn * bv.x) * inv;
        o.y = (c1 + dn * bv.y) * inv;
        o.z = (c2 + dn * bv.z) * inv;
        o.w = (c3 + dn * bv.w) * inv;
        *(float4*)&out[(size_t)row * OUT_DIM + colBase + tx * 4] = o;
    }
}

// ---------------- launch: 4 kernels ----------------
extern "C" void kernel_launch(void* const* d_in, const int* in_sizes, int n_in,
                              void* d_out, int out_size) {
    (void)in_sizes; (void)n_in; (void)out_size;
    const float* feats = (const float*)d_in[0];
    const float* W     = (const float*)d_in[1];
    const float* b     = (const float*)d_in[2];
    const float* a     = (const float*)d_in[3];
    const void*  r     = d_in[4];
    const void*  c     = d_in[5];
    const void*  bidx  = d_in[6];
    float* out = (float*)d_out;

    k_front<<<FRONT_GRID, 256>>>(W, b, a, r, bidx);
    k_edge<<<(N_EDGES / 4 + 255) / 256, 256>>>(r, c);
    k_agg<<<BATCH / 4, 128>>>(feats, bidx);
    k_gemm<<<(BATCH / GBM) * 2, 256>>>(W, b, out);
}